// round 14
// baseline (speedup 1.0000x reference)
#include <cuda_runtime.h>
#include <cuda_fp16.h>
#include <cstdint>

// ---------------------------------------------------------------------------
// Problem constants
// ---------------------------------------------------------------------------
#define NEURONS  512
#define CHANNELS 384
#define HWSZ     169
#define BATCH    512
#define K_TOTAL  (CHANNELS * HWSZ)      // 64896

// GEMM tiling: CTA 128x128, 4 warps of 64x64, k-tile = 64 halves (128 B row)
#define BM 128
#define BN 128
#define KH 64
#define TILES64 (K_TOTAL / KH)           // 1014
#define SPLITS 18                        // 6 splits of 57 tiles + 12 of 56
#define STAGES 3

#define A_BYTES (BM * 128)               // 16 KB (fp16)
#define B_BYTES (BN * 128)               // 16 KB
#define STAGE_BYTES (A_BYTES + B_BYTES)  // 32 KB
#define SMEM_TOTAL (STAGES * STAGE_BYTES)// 96 KB

// prep grid split: convert x (16 elems/thread) | build g_w | init out with bias
#define CONV_BLOCKS ((BATCH * K_TOTAL) / (256 * 16))          // 8112
#define W_BLOCKS    (NEURONS * 4)                             // 2048
#define OUT_BLOCKS  ((BATCH * NEURONS) / (256 * 4))           // 256
#define PREP_BLOCKS (CONV_BLOCKS + W_BLOCKS + OUT_BLOCKS)     // 10416

// Scratch (__device__ globals per allocation rules)
__device__ __half g_x[(size_t)BATCH * K_TOTAL];      // x converted to fp16
__device__ __half g_w[(size_t)NEURONS * K_TOTAL];    // rank-1 weights, fp16

// ---------------------------------------------------------------------------
// Helpers (baseline PTX: sm_80-class; compute_103 target has no 'a' isa)
// ---------------------------------------------------------------------------
__device__ __forceinline__ uint32_t s2u(const void* p) {
    return (uint32_t)__cvta_generic_to_shared(p);
}

// Full SW128 swizzle: conflict-free for row fills and ldmatrix column reads.
__device__ __forceinline__ uint32_t sw_off(uint32_t row, uint32_t c16) {
    return row * 128u + ((c16 ^ (row & 7u)) << 4);
}

// pack two fp32 into one f16x2 reg: {hi, lo}
__device__ __forceinline__ uint32_t pack_f16(float hi, float lo) {
    uint32_t d;
    asm("cvt.rn.f16x2.f32 %0, %1, %2;" : "=r"(d) : "f"(hi), "f"(lo));
    return d;
}

#define CPA16(dst, src) \
    asm volatile("cp.async.cg.shared.global [%0], [%1], 16;" :: "r"(dst), "l"(src))
#define CP_COMMIT()  asm volatile("cp.async.commit_group;" ::: "memory")
#define CP_WAIT(n)   asm volatile("cp.async.wait_group %0;" :: "n"(n) : "memory")

#define LDSM_X4(r0, r1, r2, r3, a) \
    asm volatile("ldmatrix.sync.aligned.m8n8.x4.shared.b16 {%0,%1,%2,%3}, [%4];" \
                 : "=r"(r0), "=r"(r1), "=r"(r2), "=r"(r3) : "r"(a))

// fp16 MMA: m16n8k16, f32 accum
#define MMA_F16(c, a, b) \
    asm volatile("mma.sync.aligned.m16n8k16.row.col.f32.f16.f16.f32 " \
                 "{%0,%1,%2,%3},{%4,%5,%6,%7},{%8,%9},{%0,%1,%2,%3};" \
                 : "+f"((c)[0]), "+f"((c)[1]), "+f"((c)[2]), "+f"((c)[3]) \
                 : "r"((a)[0]), "r"((a)[1]), "r"((a)[2]), "r"((a)[3]), \
                   "r"((b)[0]), "r"((b)[1]))

// fire-and-forget global fp32 reduction (REDG, sm_60+ baseline)
#define REDADD(p, v) \
    asm volatile("red.global.add.f32 [%0], %1;" :: "l"(p), "f"(v) : "memory")

// ---------------------------------------------------------------------------
// Kernel 1: merged prep.
//   [0, CONV_BLOCKS): convert x fp32 -> fp16, 16 elems/thread (MLP=4).
//   [CONV_BLOCKS, +W_BLOCKS): g_w[n][k] = fp16(W_d[n,c]*W_s[n,hw]).
//   [.., +OUT_BLOCKS): out[b,n] = W_b[n]  (bias init; GEMM atomically adds).
// ---------------------------------------------------------------------------
__global__ void __launch_bounds__(256) prep(const float* __restrict__ x,
                                            const float* __restrict__ W_s,
                                            const float* __restrict__ W_d,
                                            const float* __restrict__ W_b,
                                            float* __restrict__ out) {
    if (blockIdx.x < CONV_BLOCKS) {
        const size_t idx = (size_t)blockIdx.x * 256 + threadIdx.x; // 16-elem slot
        const float4* src = (const float4*)x + idx * 4;
        float4 v0 = src[0];
        float4 v1 = src[1];
        float4 v2 = src[2];
        float4 v3 = src[3];
        uint4 o0, o1;
        o0.x = pack_f16(v0.y, v0.x);  o0.y = pack_f16(v0.w, v0.z);
        o0.z = pack_f16(v1.y, v1.x);  o0.w = pack_f16(v1.w, v1.z);
        o1.x = pack_f16(v2.y, v2.x);  o1.y = pack_f16(v2.w, v2.z);
        o1.z = pack_f16(v3.y, v3.x);  o1.w = pack_f16(v3.w, v3.z);
        ((uint4*)g_x)[idx * 2]     = o0;
        ((uint4*)g_x)[idx * 2 + 1] = o1;
    } else if (blockIdx.x < CONV_BLOCKS + W_BLOCKS) {
        const int bid2 = blockIdx.x - CONV_BLOCKS;
        const int n = bid2 >> 2;
        const int q = bid2 & 3;
        __shared__ float ws[HWSZ];
        __shared__ float wd[CHANNELS];
        for (int i = threadIdx.x; i < HWSZ; i += 256)     ws[i] = W_s[n * HWSZ + i];
        for (int i = threadIdx.x; i < CHANNELS; i += 256) wd[i] = W_d[n * CHANNELS + i];
        __syncthreads();
        const int QK = K_TOTAL / 4;                      // 16224
        const int kbase = q * QK;
        uint4* dst = (uint4*)(g_w + (size_t)n * K_TOTAL + kbase);
        for (int v = threadIdx.x; v < QK / 8; v += 256) {
            int k = kbase + v * 8;
            float r[8];
            #pragma unroll
            for (int i = 0; i < 8; i++) {
                int ki = k + i;
                int c  = ki / HWSZ;                      // constant divisor -> mul-hi
                int hw = ki - c * HWSZ;
                r[i] = wd[c] * ws[hw];
            }
            uint4 o;
            o.x = pack_f16(r[1], r[0]);
            o.y = pack_f16(r[3], r[2]);
            o.z = pack_f16(r[5], r[4]);
            o.w = pack_f16(r[7], r[6]);
            dst[v] = o;
        }
    } else {
        const int i4 = (blockIdx.x - CONV_BLOCKS - W_BLOCKS) * 256 + threadIdx.x;
        const int n4 = i4 & (NEURONS / 4 - 1);
        ((float4*)out)[i4] = ((const float4*)W_b)[n4];
    }
}

// ---------------------------------------------------------------------------
// Kernel 2: fp16 mma.sync split-K GEMM. 128 threads = 4 warps of 64x64.
// Deep prefetch: fill(t+2) issued BEFORE the wait; CP_WAIT(2) gates only on
// fill(t), keeping 2 tiles in flight. Epilogue: red.global.add.f32 into out.
// ---------------------------------------------------------------------------
__global__ void __launch_bounds__(128, 2) gemm_f16(float* __restrict__ out) {
    extern __shared__ char smem[];
    const uint32_t sbase = s2u(smem);

    const int tid  = threadIdx.x;
    const int wid  = tid >> 5;
    const int lane = tid & 31;
    const int n0 = blockIdx.x * BN;
    const int m0 = blockIdx.y * BM;
    const int s  = blockIdx.z;

    // uneven split-K over 1014 k64-tiles: first 6 splits get 57, rest 56
    const int NT  = 56 + (s < 6 ? 1 : 0);
    const int ts0 = 56 * s + (s < 6 ? s : 6);

    const __half* xbase = g_x + (size_t)m0 * K_TOTAL + (size_t)ts0 * KH;
    const __half* wbase = g_w + (size_t)n0 * K_TOTAL + (size_t)ts0 * KH;

    const int wm = (wid & 1) * 64;        // warp m offset
    const int wn = (wid >> 1) * 64;       // warp n offset
    const int sub = lane >> 3;            // 0..3
    const int r8  = lane & 7;

    float acc[4][8][4];                   // 4 m16 x 8 n8 fragments
    #pragma unroll
    for (int i = 0; i < 4; i++)
        #pragma unroll
        for (int j = 0; j < 8; j++)
            #pragma unroll
            for (int f = 0; f < 4; f++) acc[i][j][f] = 0.f;

    // stage fill: A 1024 + B 1024 16B chunks; 16 per thread
    auto fill = [&](int t) {
        const uint32_t sa = sbase + (t % STAGES) * STAGE_BYTES;
        const uint32_t sB = sa + A_BYTES;
        const __half* xs = xbase + (size_t)t * KH;
        const __half* wr = wbase + (size_t)t * KH;
        #pragma unroll
        for (int i = 0; i < 8; i++) {
            int slot = tid + i * 128;            // 0..1023
            uint32_t row = slot >> 3, c = slot & 7;
            uint32_t off = sw_off(row, c);
            CPA16(sa + off, xs + (size_t)row * K_TOTAL + c * 8);
            CPA16(sB + off, wr + (size_t)row * K_TOTAL + c * 8);
        }
        CP_COMMIT();
    };

    fill(0);
    fill(1);

    for (int t = 0; t < NT; t++) {
        // Issue next fill first (stage (t+2)%3 == (t-1)%3, freed by the
        // trailing __syncthreads of iteration t-1), then gate only on fill(t).
        if (t + 2 < NT) {
            fill(t + 2);
            CP_WAIT(2);
        } else if (t + 1 < NT) {
            CP_WAIT(1);
        } else {
            CP_WAIT(0);
        }
        __syncthreads();

        const uint32_t sa = sbase + (t % STAGES) * STAGE_BYTES;
        const uint32_t sB = sa + A_BYTES;

        #pragma unroll
        for (int ks = 0; ks < 4; ks++) {         // four k16 steps per k64 tile
            // A: 4 m16k16 fragments (m-half = sub&1, k-chunk = sub>>1)
            uint32_t a[4][4];
            #pragma unroll
            for (int i = 0; i < 4; i++) {
                uint32_t row   = wm + i * 16 + (sub & 1) * 8 + r8;
                uint32_t chunk = ks * 2 + (sub >> 1);
                LDSM_X4(a[i][0], a[i][1], a[i][2], a[i][3],
                        sa + sw_off(row, chunk));
            }
            // B: 8 n8k16 fragments via 4 LDSM.x4 (n-half = sub>>1, k-chunk = sub&1)
            uint32_t b[8][2];
            #pragma unroll
            for (int p = 0; p < 4; p++) {
                uint32_t row   = wn + p * 16 + (sub >> 1) * 8 + r8;
                uint32_t chunk = ks * 2 + (sub & 1);
                uint32_t t0, t1, t2, t3;
                LDSM_X4(t0, t1, t2, t3, sB + sw_off(row, chunk));
                b[p * 2 + 0][0] = t0;  b[p * 2 + 0][1] = t1;
                b[p * 2 + 1][0] = t2;  b[p * 2 + 1][1] = t3;
            }
            #pragma unroll
            for (int i = 0; i < 4; i++)
                #pragma unroll
                for (int j = 0; j < 8; j++)
                    MMA_F16(acc[i][j], a[i], b[j]);
        }
        __syncthreads();
    }

    // epilogue: atomically accumulate the 64x64 warp tile into out
    const int g  = lane >> 2;
    const int t4 = lane & 3;
    #pragma unroll
    for (int i = 0; i < 4; i++) {
        #pragma unroll
        for (int j = 0; j < 8; j++) {
            int row = m0 + wm + i * 16 + g;
            int col = n0 + wn + j * 8 + t4 * 2;
            float* p0 = out + (size_t)row * NEURONS + col;
            float* p1 = out + (size_t)(row + 8) * NEURONS + col;
            REDADD(p0,     acc[i][j][0]);
            REDADD(p0 + 1, acc[i][j][1]);
            REDADD(p1,     acc[i][j][2]);
            REDADD(p1 + 1, acc[i][j][3]);
        }
    }
}

// ---------------------------------------------------------------------------
// Entry point
// ---------------------------------------------------------------------------
extern "C" void kernel_launch(void* const* d_in, const int* in_sizes, int n_in,
                              void* d_out, int out_size) {
    const float* x   = (const float*)d_in[0];   // [512, 384, 13, 13]
    const float* W_s = (const float*)d_in[1];   // [512, 13, 13]
    const float* W_d = (const float*)d_in[2];   // [512, 384]
    const float* W_b = (const float*)d_in[3];   // [1, 512]
    float* out = (float*)d_out;                 // [512, 512]

    (void)cudaFuncSetAttribute(gemm_f16,
        cudaFuncAttributeMaxDynamicSharedMemorySize, SMEM_TOTAL);

    prep<<<PREP_BLOCKS, 256>>>(x, W_s, W_d, W_b, out);

    dim3 grid(NEURONS / BN, BATCH / BM, SPLITS);   // 4 x 4 x 18 = 288 CTAs
    gemm_f16<<<grid, 128, SMEM_TOTAL>>>(out);
}

// round 15
// speedup vs baseline: 1.0542x; 1.0542x over previous
#include <cuda_runtime.h>
#include <cuda_fp16.h>
#include <cstdint>

// ---------------------------------------------------------------------------
// Problem constants
// ---------------------------------------------------------------------------
#define NEURONS  512
#define CHANNELS 384
#define HWSZ     169
#define BATCH    512
#define K_TOTAL  (CHANNELS * HWSZ)      // 64896

// GEMM tiling: CTA 128x128, 4 warps of 64x64, k-tile = 64 (KH)
// A consumed as fp32 directly from x; B fp16 from g_w (pi-permuted storage).
#define BM 128
#define BN 128
#define KH 64
#define SPLITS 18                        // 6 splits of 57 k64-tiles + 12 of 56
#define STAGES 2

#define A_BYTES (BM * 2 * 128)           // fp32 tile: 2 k-panels x 128 rows x 128B = 32 KB
#define B_BYTES (BN * 128)               // fp16 tile: 16 KB
#define STAGE_BYTES (A_BYTES + B_BYTES)  // 48 KB
#define SMEM_TOTAL (STAGES * STAGE_BYTES)// 96 KB

// prep grid: build g_w (pi-permuted) | init out with bias
#define W_BLOCKS    (NEURONS * 4)                             // 2048
#define OUT_BLOCKS  ((BATCH * NEURONS) / (256 * 4))           // 256
#define PREP_BLOCKS (W_BLOCKS + OUT_BLOCKS)                   // 2304

// Scratch (__device__ globals per allocation rules)
__device__ __half g_w[(size_t)NEURONS * K_TOTAL];    // rank-1 weights, fp16, pi-permuted per k16

// ---------------------------------------------------------------------------
// Helpers (baseline PTX: sm_80-class; compute_103 target has no 'a' isa)
// ---------------------------------------------------------------------------
__device__ __forceinline__ uint32_t s2u(const void* p) {
    return (uint32_t)__cvta_generic_to_shared(p);
}

// Full SW128 swizzle within a 128-row x 128B panel: conflict-free for
// cp.async row fills and ldmatrix 8x8 column reads.
__device__ __forceinline__ uint32_t sw_off(uint32_t row, uint32_t c16) {
    return row * 128u + ((c16 ^ (row & 7u)) << 4);
}

// pack two fp32 into one f16x2 reg: {hi, lo}
__device__ __forceinline__ uint32_t pack_f16(float hi, float lo) {
    uint32_t d;
    asm("cvt.rn.f16x2.f32 %0, %1, %2;" : "=r"(d) : "f"(hi), "f"(lo));
    return d;
}

#define CPA16(dst, src) \
    asm volatile("cp.async.cg.shared.global [%0], [%1], 16;" :: "r"(dst), "l"(src))
#define CP_COMMIT()  asm volatile("cp.async.commit_group;" ::: "memory")
#define CP_WAIT(n)   asm volatile("cp.async.wait_group %0;" :: "n"(n) : "memory")

#define LDSM_X4(r0, r1, r2, r3, a) \
    asm volatile("ldmatrix.sync.aligned.m8n8.x4.shared.b16 {%0,%1,%2,%3}, [%4];" \
                 : "=r"(r0), "=r"(r1), "=r"(r2), "=r"(r3) : "r"(a))

// fp16 MMA: m16n8k16, f32 accum
#define MMA_F16(c, a, b) \
    asm volatile("mma.sync.aligned.m16n8k16.row.col.f32.f16.f16.f32 " \
                 "{%0,%1,%2,%3},{%4,%5,%6,%7},{%8,%9},{%0,%1,%2,%3};" \
                 : "+f"((c)[0]), "+f"((c)[1]), "+f"((c)[2]), "+f"((c)[3]) \
                 : "r"((a)[0]), "r"((a)[1]), "r"((a)[2]), "r"((a)[3]), \
                   "r"((b)[0]), "r"((b)[1]))

// fire-and-forget global fp32 reduction (REDG, sm_60+ baseline)
#define REDADD(p, v) \
    asm volatile("red.global.add.f32 [%0], %1;" :: "l"(p), "f"(v) : "memory")

// ---------------------------------------------------------------------------
// Kernel 1: prep.
//   [0, W_BLOCKS): g_w[n][k16 groups] = fp16(W_d*W_s), stored with the
//     within-k16 permutation pi: stored = {r0,r4,r1,r5,r2,r6,r3,r7,
//                                          r8,r12,r9,r13,r10,r14,r11,r15}
//     matching the A-fragment k-slot assignment in the GEMM.
//   [W_BLOCKS, PREP_BLOCKS): out[b,n] = W_b[n].
// ---------------------------------------------------------------------------
__global__ void __launch_bounds__(256) prep(const float* __restrict__ W_s,
                                            const float* __restrict__ W_d,
                                            const float* __restrict__ W_b,
                                            float* __restrict__ out) {
    if (blockIdx.x < W_BLOCKS) {
        const int n = blockIdx.x >> 2;
        const int q = blockIdx.x & 3;
        __shared__ float ws[HWSZ];
        __shared__ float wd[CHANNELS];
        for (int i = threadIdx.x; i < HWSZ; i += 256)     ws[i] = W_s[n * HWSZ + i];
        for (int i = threadIdx.x; i < CHANNELS; i += 256) wd[i] = W_d[n * CHANNELS + i];
        __syncthreads();
        const int QK = K_TOTAL / 4;                      // 16224
        const int kbase = q * QK;
        uint4* dst = (uint4*)(g_w + (size_t)n * K_TOTAL + kbase);
        for (int v = threadIdx.x; v < QK / 16; v += 256) {   // 1014 k16-groups
            int k = kbase + v * 16;
            float r[16];
            #pragma unroll
            for (int i = 0; i < 16; i++) {
                int ki = k + i;
                int c  = ki / HWSZ;                      // constant divisor -> mul-hi
                int hw = ki - c * HWSZ;
                r[i] = wd[c] * ws[hw];
            }
            uint4 o0, o1;
            o0.x = pack_f16(r[4],  r[0]);
            o0.y = pack_f16(r[5],  r[1]);
            o0.z = pack_f16(r[6],  r[2]);
            o0.w = pack_f16(r[7],  r[3]);
            o1.x = pack_f16(r[12], r[8]);
            o1.y = pack_f16(r[13], r[9]);
            o1.z = pack_f16(r[14], r[10]);
            o1.w = pack_f16(r[15], r[11]);
            dst[v * 2]     = o0;
            dst[v * 2 + 1] = o1;
        }
    } else {
        const int i4 = (blockIdx.x - W_BLOCKS) * 256 + threadIdx.x;
        const int n4 = i4 & (NEURONS / 4 - 1);
        ((float4*)out)[i4] = ((const float4*)W_b)[n4];
    }
}

// ---------------------------------------------------------------------------
// Kernel 2: fp16 mma.sync split-K GEMM, A loaded fp32 from x, converted
// in-register after ldmatrix (k-permutation pi; B storage compensates).
// 128 threads = 4 warps of 64x64. 2-stage cp.async pipeline.
// ---------------------------------------------------------------------------
__global__ void __launch_bounds__(128, 2) gemm_f16(const float* __restrict__ x,
                                                   float* __restrict__ out) {
    extern __shared__ char smem[];
    const uint32_t sbase = s2u(smem);

    const int tid  = threadIdx.x;
    const int wid  = tid >> 5;
    const int lane = tid & 31;
    const int n0 = blockIdx.x * BN;
    const int m0 = blockIdx.y * BM;
    const int s  = blockIdx.z;

    // uneven split-K over 1014 k64-tiles: first 6 splits get 57, rest 56
    const int NT  = 56 + (s < 6 ? 1 : 0);
    const int ts0 = 56 * s + (s < 6 ? s : 6);

    const float*  xbase = x   + (size_t)m0 * K_TOTAL + (size_t)ts0 * KH;
    const __half* wbase = g_w + (size_t)n0 * K_TOTAL + (size_t)ts0 * KH;

    const int wm = (wid & 1) * 64;        // warp m offset
    const int wn = (wid >> 1) * 64;       // warp n offset
    const int sub = lane >> 3;            // 0..3
    const int r8  = lane & 7;

    float acc[4][8][4];                   // 4 m16 x 8 n8 fragments
    #pragma unroll
    for (int i = 0; i < 4; i++)
        #pragma unroll
        for (int j = 0; j < 8; j++)
            #pragma unroll
            for (int f = 0; f < 4; f++) acc[i][j][f] = 0.f;

    // stage fill: A 2048 fp32 16B chunks (two k-panels) + B 1024 chunks
    auto fill = [&](int t) {
        const uint32_t sa = sbase + (t & 1) * STAGE_BYTES;
        const uint32_t sB = sa + A_BYTES;
        const float*  xs = xbase + (size_t)t * KH;
        const __half* wr = wbase + (size_t)t * KH;
        #pragma unroll
        for (int i = 0; i < 16; i++) {        // A: 16 chunks/thread
            int slot = tid + i * 128;          // 0..2047
            uint32_t row = slot >> 4, c = slot & 15;
            uint32_t off = (c >> 3) * (BM * 128) + sw_off(row, c & 7);
            CPA16(sa + off, xs + (size_t)row * K_TOTAL + c * 4);
        }
        #pragma unroll
        for (int i = 0; i < 8; i++) {         // B: 8 chunks/thread
            int slot = tid + i * 128;          // 0..1023
            uint32_t row = slot >> 3, c = slot & 7;
            CPA16(sB + sw_off(row, c), wr + (size_t)row * K_TOTAL + c * 8);
        }
        CP_COMMIT();
    };

    fill(0);

    for (int t = 0; t < NT; t++) {
        CP_WAIT(0);                        // fill(t) resident (only group in flight)
        __syncthreads();
        if (t + 1 < NT) fill(t + 1);       // overlaps compute(t)

        const uint32_t sa = sbase + (t & 1) * STAGE_BYTES;
        const uint32_t sB = sa + A_BYTES;

        #pragma unroll
        for (int ks = 0; ks < 4; ks++) {     // four k16 steps per k64 tile
            // A: 4 m16k16 fragments from fp32 smem; 2 LDSM.x4 + 4 packs each.
            // LDSM matrices (sub): m-half = sub&1, chunk offset = sub>>1.
            uint32_t a[4][4];
            #pragma unroll
            for (int i = 0; i < 4; i++) {
                uint32_t row = wm + i * 16 + (sub & 1) * 8 + r8;
                uint32_t q0  = ks * 4 + (sub >> 1);
                uint32_t q1  = q0 + 2;
                uint32_t x0, x1, x2, x3, y0, y1, y2, y3;
                LDSM_X4(x0, x1, x2, x3,
                        sa + (q0 >> 3) * (BM * 128) + sw_off(row, q0 & 7));
                LDSM_X4(y0, y1, y2, y3,
                        sa + (q1 >> 3) * (BM * 128) + sw_off(row, q1 & 7));
                // pi: spec kappa=2t4 <- k=t4 (lo), kappa=2t4+1 <- k=t4+4 (hi)
                a[i][0] = pack_f16(__uint_as_float(x2), __uint_as_float(x0));
                a[i][1] = pack_f16(__uint_as_float(x3), __uint_as_float(x1));
                a[i][2] = pack_f16(__uint_as_float(y2), __uint_as_float(y0));
                a[i][3] = pack_f16(__uint_as_float(y3), __uint_as_float(y1));
            }
            // B: 8 n8k16 fragments via 4 LDSM.x4 (storage already pi-permuted)
            uint32_t b[8][2];
            #pragma unroll
            for (int p = 0; p < 4; p++) {
                uint32_t row   = wn + p * 16 + (sub >> 1) * 8 + r8;
                uint32_t chunk = ks * 2 + (sub & 1);
                uint32_t t0, t1, t2, t3;
                LDSM_X4(t0, t1, t2, t3, sB + sw_off(row, chunk));
                b[p * 2 + 0][0] = t0;  b[p * 2 + 0][1] = t1;
                b[p * 2 + 1][0] = t2;  b[p * 2 + 1][1] = t3;
            }
            #pragma unroll
            for (int i = 0; i < 4; i++)
                #pragma unroll
                for (int j = 0; j < 8; j++)
                    MMA_F16(acc[i][j], a[i], b[j]);
        }
        __syncthreads();
    }

    // epilogue: atomically accumulate the 64x64 warp tile into out
    const int g  = lane >> 2;
    const int t4 = lane & 3;
    #pragma unroll
    for (int i = 0; i < 4; i++) {
        #pragma unroll
        for (int j = 0; j < 8; j++) {
            int row = m0 + wm + i * 16 + g;
            int col = n0 + wn + j * 8 + t4 * 2;
            float* p0 = out + (size_t)row * NEURONS + col;
            float* p1 = out + (size_t)(row + 8) * NEURONS + col;
            REDADD(p0,     acc[i][j][0]);
            REDADD(p0 + 1, acc[i][j][1]);
            REDADD(p1,     acc[i][j][2]);
            REDADD(p1 + 1, acc[i][j][3]);
        }
    }
}

// ---------------------------------------------------------------------------
// Entry point
// ---------------------------------------------------------------------------
extern "C" void kernel_launch(void* const* d_in, const int* in_sizes, int n_in,
                              void* d_out, int out_size) {
    const float* x   = (const float*)d_in[0];   // [512, 384, 13, 13]
    const float* W_s = (const float*)d_in[1];   // [512, 13, 13]
    const float* W_d = (const float*)d_in[2];   // [512, 384]
    const float* W_b = (const float*)d_in[3];   // [1, 512]
    float* out = (float*)d_out;                 // [512, 512]

    (void)cudaFuncSetAttribute(gemm_f16,
        cudaFuncAttributeMaxDynamicSharedMemorySize, SMEM_TOTAL);

    prep<<<PREP_BLOCKS, 256>>>(W_s, W_d, W_b, out);

    dim3 grid(NEURONS / BN, BATCH / BM, SPLITS);   // 4 x 4 x 18 = 288 CTAs
    gemm_f16<<<grid, 128, SMEM_TOTAL>>>(x, out);
}